// round 1
// baseline (speedup 1.0000x reference)
#include <cuda_runtime.h>
#include <cuda_bf16.h>
#include <cstdint>
#include <cstdio>

// Problem constants (fixed by the dataset)
#define NN_MAX 10000
#define EE_MAX 120000

// ---------------- scratch (device globals; no allocation allowed) ----------------
__device__ float g_h1[(size_t)EE_MAX * 128];        // 61.4 MB
__device__ float g_h2[(size_t)EE_MAX * 256];        // 122.9 MB
__device__ float g_we[(size_t)EE_MAX * 1024];       // 491.5 MB
__device__ float g_h[(size_t)NN_MAX * 32];
__device__ float g_aggr[(size_t)NN_MAX * 32];
__device__ float g_cnt[(size_t)NN_MAX];

// ---------------- small helpers ----------------
__device__ __forceinline__ uint32_t f2tf32(float x) {
    uint32_t r;
    asm volatile("cvt.rna.tf32.f32 %0, %1;" : "=r"(r) : "f"(x));
    return r;
}

__device__ __forceinline__ void mma_m16n8k8_tf32(float* c, const uint32_t* a, const uint32_t* b) {
    asm volatile(
        "mma.sync.aligned.m16n8k8.row.col.f32.tf32.tf32.f32 "
        "{%0,%1,%2,%3}, {%4,%5,%6,%7}, {%8,%9}, {%0,%1,%2,%3};\n"
        : "+f"(c[0]), "+f"(c[1]), "+f"(c[2]), "+f"(c[3])
        : "r"(a[0]), "r"(a[1]), "r"(a[2]), "r"(a[3]), "r"(b[0]), "r"(b[1]));
}

__device__ __forceinline__ void cp_async16(float* smem_dst, const float* gmem_src, int src_bytes) {
    uint32_t s = (uint32_t)__cvta_generic_to_shared(smem_dst);
    asm volatile("cp.async.cg.shared.global [%0], [%1], 16, %2;\n"
                 :: "r"(s), "l"(gmem_src), "r"(src_bytes));
}
__device__ __forceinline__ void cp_commit() { asm volatile("cp.async.commit_group;\n"); }
__device__ __forceinline__ void cp_wait1() { asm volatile("cp.async.wait_group 1;\n"); }
__device__ __forceinline__ void cp_wait0() { asm volatile("cp.async.wait_group 0;\n"); }

// ---------------- tiled tf32 GEMM: C[M,N] = op(A[M,K] @ B[K,N] + bias) ----------------
// BM=128, BN=128, BK=32, 256 threads, warps 2(m) x 4(n), warp tile 64x32.
#define GB_BM 128
#define GB_BN 128
#define GB_BK 32
#define SA_STRIDE 36   // conflict-free for A-frag pattern (4*row + col mod 32 unique)
#define SB_STRIDE 136  // conflict-free for B-frag pattern (8*k + n mod 32 unique)
#define GEMM_SMEM ((2 * GB_BM * SA_STRIDE + 2 * GB_BK * SB_STRIDE) * 4)

__device__ __forceinline__ void gemm_loadA(const float* A, float* sA, int m0, int kt,
                                           int tid, int M, int K) {
#pragma unroll
    for (int i = 0; i < 4; ++i) {
        int idx = i * 256 + tid;
        int r = idx >> 3;          // 8 float4 per row of 32
        int kq = idx & 7;
        int gr = m0 + r;
        int grc = gr < M ? gr : (M - 1);
        const float* gp = A + (size_t)grc * K + kt * GB_BK + kq * 4;
        float* sp = sA + r * SA_STRIDE + kq * 4;
        cp_async16(sp, gp, gr < M ? 16 : 0);
    }
}

__device__ __forceinline__ void gemm_loadB(const float* B, float* sB, int n0, int kt,
                                           int tid, int N) {
#pragma unroll
    for (int i = 0; i < 4; ++i) {
        int idx = i * 256 + tid;
        int r = idx >> 5;          // 32 float4 per row of 128
        int nq = idx & 31;
        const float* gp = B + (size_t)(kt * GB_BK + r) * N + n0 + nq * 4;
        float* sp = sB + r * SB_STRIDE + nq * 4;
        cp_async16(sp, gp, 16);
    }
}

template <bool RELU>
__global__ void __launch_bounds__(256, 2)
gemm_tf32_kernel(const float* __restrict__ A, const float* __restrict__ B,
                 const float* __restrict__ bias, float* __restrict__ C,
                 int M, int N, int K) {
    extern __shared__ float smem[];
    float* sA = smem;                              // [2][128][36]
    float* sB = smem + 2 * GB_BM * SA_STRIDE;      // [2][32][136]

    const int tid = threadIdx.x;
    const int warp = tid >> 5;
    const int lane = tid & 31;
    const int wm = (warp >> 2) * 64;   // 0 / 64
    const int wn = (warp & 3) * 32;    // 0..96
    const int m0 = blockIdx.y * GB_BM;
    const int n0 = blockIdx.x * GB_BN;

    float acc[4][4][4];
#pragma unroll
    for (int mt = 0; mt < 4; ++mt)
#pragma unroll
        for (int nt = 0; nt < 4; ++nt)
#pragma unroll
            for (int r = 0; r < 4; ++r) acc[mt][nt][r] = 0.f;

    const int KT = K / GB_BK;

    gemm_loadA(A, sA, m0, 0, tid, M, K);
    gemm_loadB(B, sB, n0, 0, tid, N);
    cp_commit();

    for (int kt = 0; kt < KT; ++kt) {
        int buf = kt & 1;
        if (kt + 1 < KT) {
            gemm_loadA(A, sA + (buf ^ 1) * GB_BM * SA_STRIDE, m0, kt + 1, tid, M, K);
            gemm_loadB(B, sB + (buf ^ 1) * GB_BK * SB_STRIDE, n0, kt + 1, tid, N);
            cp_commit();
            cp_wait1();
        } else {
            cp_wait0();
        }
        __syncthreads();

        const float* a_s = sA + buf * GB_BM * SA_STRIDE;
        const float* b_s = sB + buf * GB_BK * SB_STRIDE;

#pragma unroll
        for (int ks = 0; ks < GB_BK / 8; ++ks) {
            uint32_t afrag[4][4], bfrag[4][2];
#pragma unroll
            for (int mt = 0; mt < 4; ++mt) {
                int row = wm + mt * 16 + (lane >> 2);
                int col = ks * 8 + (lane & 3);
                afrag[mt][0] = f2tf32(a_s[row * SA_STRIDE + col]);
                afrag[mt][1] = f2tf32(a_s[(row + 8) * SA_STRIDE + col]);
                afrag[mt][2] = f2tf32(a_s[row * SA_STRIDE + col + 4]);
                afrag[mt][3] = f2tf32(a_s[(row + 8) * SA_STRIDE + col + 4]);
            }
#pragma unroll
            for (int nt = 0; nt < 4; ++nt) {
                int nn = wn + nt * 8 + (lane >> 2);
                int kk = ks * 8 + (lane & 3);
                bfrag[nt][0] = f2tf32(b_s[kk * SB_STRIDE + nn]);
                bfrag[nt][1] = f2tf32(b_s[(kk + 4) * SB_STRIDE + nn]);
            }
#pragma unroll
            for (int mt = 0; mt < 4; ++mt)
#pragma unroll
                for (int nt = 0; nt < 4; ++nt)
                    mma_m16n8k8_tf32(acc[mt][nt], afrag[mt], bfrag[nt]);
        }
        __syncthreads();
    }

    // epilogue: bias (+ optional relu)
#pragma unroll
    for (int mt = 0; mt < 4; ++mt) {
        int r0 = m0 + wm + mt * 16 + (lane >> 2);
#pragma unroll
        for (int nt = 0; nt < 4; ++nt) {
            int c0 = n0 + wn + nt * 8 + (lane & 3) * 2;
            float bv0 = bias[c0], bv1 = bias[c0 + 1];
            if (r0 < M) {
                float v0 = acc[mt][nt][0] + bv0;
                float v1 = acc[mt][nt][1] + bv1;
                if (RELU) { v0 = fmaxf(v0, 0.f); v1 = fmaxf(v1, 0.f); }
                C[(size_t)r0 * N + c0] = v0;
                C[(size_t)r0 * N + c0 + 1] = v1;
            }
            if (r0 + 8 < M) {
                float v2 = acc[mt][nt][2] + bv0;
                float v3 = acc[mt][nt][3] + bv1;
                if (RELU) { v2 = fmaxf(v2, 0.f); v3 = fmaxf(v3, 0.f); }
                C[(size_t)(r0 + 8) * N + c0] = v2;
                C[(size_t)(r0 + 8) * N + c0 + 1] = v3;
            }
        }
    }
}

// ---------------- elementwise / small kernels ----------------
__global__ void zero_kernel(float* p, int n) {
    int i = blockIdx.x * blockDim.x + threadIdx.x;
    if (i < n) p[i] = 0.f;
}

__global__ void count_deg_kernel(const int* __restrict__ dst, float* __restrict__ cnt, int E) {
    int e = blockIdx.x * blockDim.x + threadIdx.x;
    if (e < E) atomicAdd(&cnt[dst[e]], 1.0f);
}

// h0 = x @ fc1_w + fc1_b    (x: [N,6], fc1_w: [6,32])
__global__ void node_init_kernel(const float* __restrict__ x, const float* __restrict__ w,
                                 const float* __restrict__ b, float* __restrict__ h, int Nn) {
    int i = blockIdx.x * blockDim.x + threadIdx.x;
    if (i >= Nn * 32) return;
    int n = i >> 5, o = i & 31;
    float acc = b[o];
#pragma unroll
    for (int k = 0; k < 6; ++k) acc += x[n * 6 + k] * w[k * 32 + o];
    h[i] = acc;
}

// h1 = relu(edge_attr @ k1_w + k1_b)   (edge_attr: [E,6], k1_w: [6,128])
__global__ void edge_l1_kernel(const float* __restrict__ ea, const float* __restrict__ w,
                               const float* __restrict__ b, float* __restrict__ h1, int E) {
    int i = blockIdx.x * blockDim.x + threadIdx.x;
    if (i >= E * 128) return;
    int e = i >> 7, j = i & 127;
    float acc = b[j];
#pragma unroll
    for (int k = 0; k < 6; ++k) acc += ea[e * 6 + k] * w[k * 128 + j];
    h1[i] = fmaxf(acc, 0.f);
}

// one warp per edge: msg = h[src] @ W_e (32x32), atomic scatter into aggr[dst]
__global__ void scatter_kernel(const float* __restrict__ h, const float* __restrict__ we,
                               const int* __restrict__ src, const int* __restrict__ dst,
                               float* __restrict__ aggr, int E) {
    int e = blockIdx.x * 8 + (threadIdx.x >> 5);
    if (e >= E) return;
    int lane = threadIdx.x & 31;
    int s = src[e];
    float hv = h[s * 32 + lane];
    const float* W = we + (size_t)e * 1024;
    float msg = 0.f;
#pragma unroll
    for (int i = 0; i < 32; ++i) {
        float hi = __shfl_sync(0xffffffffu, hv, i);
        msg += hi * W[i * 32 + lane];
    }
    atomicAdd(&aggr[dst[e] * 32 + lane], msg);
}

// h = aggr/denom + h @ root_w + conv_b  (+ relu except last depth)
__global__ void update_kernel(const float* __restrict__ aggr, const float* __restrict__ cnt,
                              const float* __restrict__ rootw, const float* __restrict__ bias,
                              float* __restrict__ h, int Nn, int do_relu) {
    int n = blockIdx.x * 8 + (threadIdx.x >> 5);
    if (n >= Nn) return;
    int lane = threadIdx.x & 31;
    float hv = h[n * 32 + lane];
    float r = 0.f;
#pragma unroll
    for (int i = 0; i < 32; ++i) {
        float hi = __shfl_sync(0xffffffffu, hv, i);
        r += hi * rootw[i * 32 + lane];
    }
    float den = fmaxf(cnt[n], 1.0f);
    float v = aggr[n * 32 + lane] / den + r + bias[lane];
    if (do_relu) v = fmaxf(v, 0.f);
    h[n * 32 + lane] = v;
}

// out[n] = relu(h @ fc2 + b2) @ fc3 + b3
__global__ void readout_kernel(const float* __restrict__ h, const float* __restrict__ w2,
                               const float* __restrict__ b2, const float* __restrict__ w3,
                               const float* __restrict__ b3, float* __restrict__ out, int Nn) {
    int n = blockIdx.x * 8 + (threadIdx.x >> 5);
    if (n >= Nn) return;
    int lane = threadIdx.x & 31;
    float hv = h[n * 32 + lane];
    float acc = 0.f;
#pragma unroll
    for (int jt = 0; jt < 4; ++jt) {
        int j = jt * 32 + lane;
        float y = b2[j];
#pragma unroll
        for (int i = 0; i < 32; ++i) {
            float hi = __shfl_sync(0xffffffffu, hv, i);
            y += hi * w2[i * 128 + j];
        }
        y = fmaxf(y, 0.f);
        acc += y * w3[j];
    }
#pragma unroll
    for (int off = 16; off; off >>= 1) acc += __shfl_down_sync(0xffffffffu, acc, off);
    if (lane == 0) out[n] = acc + b3[0];
}

// ---------------- launch ----------------
extern "C" void kernel_launch(void* const* d_in, const int* in_sizes, int n_in,
                              void* d_out, int out_size) {
    const float* x     = (const float*)d_in[0];
    const int*   ei    = (const int*)d_in[1];
    const float* ea    = (const float*)d_in[2];
    const float* fc1w  = (const float*)d_in[3];
    const float* fc1b  = (const float*)d_in[4];
    const float* k1w   = (const float*)d_in[5];
    const float* k1b   = (const float*)d_in[6];
    const float* k2w   = (const float*)d_in[7];
    const float* k2b   = (const float*)d_in[8];
    const float* k3w   = (const float*)d_in[9];
    const float* k3b   = (const float*)d_in[10];
    const float* rootw = (const float*)d_in[11];
    const float* convb = (const float*)d_in[12];
    const float* fc2w  = (const float*)d_in[13];
    const float* fc2b  = (const float*)d_in[14];
    const float* fc3w  = (const float*)d_in[15];
    const float* fc3b  = (const float*)d_in[16];
    float* out = (float*)d_out;

    const int Nn = in_sizes[0] / 6;        // 10000
    const int E  = in_sizes[2] / 6;        // 120000
    const int* src = ei;
    const int* dst = ei + E;

    float *p_h1, *p_h2, *p_we, *p_h, *p_aggr, *p_cnt;
    cudaGetSymbolAddress((void**)&p_h1, g_h1);
    cudaGetSymbolAddress((void**)&p_h2, g_h2);
    cudaGetSymbolAddress((void**)&p_we, g_we);
    cudaGetSymbolAddress((void**)&p_h, g_h);
    cudaGetSymbolAddress((void**)&p_aggr, g_aggr);
    cudaGetSymbolAddress((void**)&p_cnt, g_cnt);

    cudaFuncSetAttribute(gemm_tf32_kernel<true>,
                         cudaFuncAttributeMaxDynamicSharedMemorySize, GEMM_SMEM);
    cudaFuncSetAttribute(gemm_tf32_kernel<false>,
                         cudaFuncAttributeMaxDynamicSharedMemorySize, GEMM_SMEM);

    // degree (scatter-mean denominator)
    zero_kernel<<<(Nn + 255) / 256, 256>>>(p_cnt, Nn);
    count_deg_kernel<<<(E + 255) / 256, 256>>>(dst, p_cnt, E);

    // node embedding
    node_init_kernel<<<(Nn * 32 + 255) / 256, 256>>>(x, fc1w, fc1b, p_h, Nn);

    // edge MLP
    edge_l1_kernel<<<(E * 128 + 255) / 256, 256>>>(ea, k1w, k1b, p_h1, E);
    {
        dim3 g(256 / GB_BN * 1 + 1, 0, 0);
        dim3 grid2(2, (E + GB_BM - 1) / GB_BM);
        gemm_tf32_kernel<true><<<grid2, 256, GEMM_SMEM>>>(p_h1, k2w, k2b, p_h2, E, 256, 128);
        dim3 grid3(8, (E + GB_BM - 1) / GB_BM);
        gemm_tf32_kernel<false><<<grid3, 256, GEMM_SMEM>>>(p_h2, k3w, k3b, p_we, E, 1024, 256);
    }

    // 4 rounds of NNConv message passing
    for (int d = 0; d < 4; ++d) {
        zero_kernel<<<(Nn * 32 + 255) / 256, 256>>>(p_aggr, Nn * 32);
        scatter_kernel<<<(E + 7) / 8, 256>>>(p_h, p_we, src, dst, p_aggr, E);
        update_kernel<<<(Nn + 7) / 8, 256>>>(p_aggr, p_cnt, rootw, convb, p_h, Nn,
                                             (d < 3) ? 1 : 0);
    }

    // readout
    readout_kernel<<<(Nn + 7) / 8, 256>>>(p_h, fc2w, fc2b, fc3w, fc3b, out, Nn);
}

// round 3
// speedup vs baseline: 1.2847x; 1.2847x over previous
#include <cuda_runtime.h>
#include <cuda_fp16.h>
#include <cstdint>

// Problem constants (fixed by the dataset)
#define NN_MAX 10000
#define EE_MAX 120000

// ---------------- scratch (device globals; no allocation allowed) ----------------
__device__ float g_h1[(size_t)EE_MAX * 128];          // 61.4 MB
__device__ float g_h2[(size_t)EE_MAX * 256];          // 122.9 MB
__device__ __half g_we[(size_t)EE_MAX * 1024];        // 245.8 MB (fp16)
__device__ float g_h[(size_t)NN_MAX * 32];
__device__ float g_aggr[(size_t)NN_MAX * 32];
__device__ float g_cnt[(size_t)NN_MAX];

// ---------------- small helpers ----------------
__device__ __forceinline__ uint32_t f2tf32(float x) {
    uint32_t r;
    asm volatile("cvt.rna.tf32.f32 %0, %1;" : "=r"(r) : "f"(x));
    return r;
}

__device__ __forceinline__ void mma_m16n8k8_tf32(float* c, const uint32_t* a, const uint32_t* b) {
    asm volatile(
        "mma.sync.aligned.m16n8k8.row.col.f32.tf32.tf32.f32 "
        "{%0,%1,%2,%3}, {%4,%5,%6,%7}, {%8,%9}, {%0,%1,%2,%3};\n"
        : "+f"(c[0]), "+f"(c[1]), "+f"(c[2]), "+f"(c[3])
        : "r"(a[0]), "r"(a[1]), "r"(a[2]), "r"(a[3]), "r"(b[0]), "r"(b[1]));
}

__device__ __forceinline__ void cp_async16(float* smem_dst, const float* gmem_src, int src_bytes) {
    uint32_t s = (uint32_t)__cvta_generic_to_shared(smem_dst);
    asm volatile("cp.async.cg.shared.global [%0], [%1], 16, %2;\n"
                 :: "r"(s), "l"(gmem_src), "r"(src_bytes));
}
__device__ __forceinline__ void cp_commit() { asm volatile("cp.async.commit_group;\n"); }
__device__ __forceinline__ void cp_wait1() { asm volatile("cp.async.wait_group 1;\n"); }
__device__ __forceinline__ void cp_wait0() { asm volatile("cp.async.wait_group 0;\n"); }

// ---------------- tiled tf32 GEMM: C[M,N] = op(A[M,K] @ B[K,N] + bias) ----------------
#define GB_BM 128
#define GB_BN 128
#define GB_BK 32
#define SA_STRIDE 36
#define SB_STRIDE 136
#define GEMM_SMEM ((2 * GB_BM * SA_STRIDE + 2 * GB_BK * SB_STRIDE) * 4)

__device__ __forceinline__ void gemm_loadA(const float* A, float* sA, int m0, int kt,
                                           int tid, int M, int K) {
#pragma unroll
    for (int i = 0; i < 4; ++i) {
        int idx = i * 256 + tid;
        int r = idx >> 3;
        int kq = idx & 7;
        int gr = m0 + r;
        int grc = gr < M ? gr : (M - 1);
        const float* gp = A + (size_t)grc * K + kt * GB_BK + kq * 4;
        float* sp = sA + r * SA_STRIDE + kq * 4;
        cp_async16(sp, gp, gr < M ? 16 : 0);
    }
}

__device__ __forceinline__ void gemm_loadB(const float* B, float* sB, int n0, int kt,
                                           int tid, int N) {
#pragma unroll
    for (int i = 0; i < 4; ++i) {
        int idx = i * 256 + tid;
        int r = idx >> 5;
        int nq = idx & 31;
        const float* gp = B + (size_t)(kt * GB_BK + r) * N + n0 + nq * 4;
        float* sp = sB + r * SB_STRIDE + nq * 4;
        cp_async16(sp, gp, 16);
    }
}

template <bool RELU, bool OUT_FP16>
__global__ void __launch_bounds__(256, 2)
gemm_tf32_kernel(const float* __restrict__ A, const float* __restrict__ B,
                 const float* __restrict__ bias, void* __restrict__ Cv,
                 int M, int N, int K) {
    extern __shared__ float smem[];
    float* sA = smem;
    float* sB = smem + 2 * GB_BM * SA_STRIDE;

    const int tid = threadIdx.x;
    const int warp = tid >> 5;
    const int lane = tid & 31;
    const int wm = (warp >> 2) * 64;
    const int wn = (warp & 3) * 32;
    const int m0 = blockIdx.y * GB_BM;
    const int n0 = blockIdx.x * GB_BN;

    float acc[4][4][4];
#pragma unroll
    for (int mt = 0; mt < 4; ++mt)
#pragma unroll
        for (int nt = 0; nt < 4; ++nt)
#pragma unroll
            for (int r = 0; r < 4; ++r) acc[mt][nt][r] = 0.f;

    const int KT = K / GB_BK;

    gemm_loadA(A, sA, m0, 0, tid, M, K);
    gemm_loadB(B, sB, n0, 0, tid, N);
    cp_commit();

    for (int kt = 0; kt < KT; ++kt) {
        int buf = kt & 1;
        if (kt + 1 < KT) {
            gemm_loadA(A, sA + (buf ^ 1) * GB_BM * SA_STRIDE, m0, kt + 1, tid, M, K);
            gemm_loadB(B, sB + (buf ^ 1) * GB_BK * SB_STRIDE, n0, kt + 1, tid, N);
            cp_commit();
            cp_wait1();
        } else {
            cp_wait0();
        }
        __syncthreads();

        const float* a_s = sA + buf * GB_BM * SA_STRIDE;
        const float* b_s = sB + buf * GB_BK * SB_STRIDE;

#pragma unroll
        for (int ks = 0; ks < GB_BK / 8; ++ks) {
            uint32_t afrag[4][4], bfrag[4][2];
#pragma unroll
            for (int mt = 0; mt < 4; ++mt) {
                int row = wm + mt * 16 + (lane >> 2);
                int col = ks * 8 + (lane & 3);
                afrag[mt][0] = f2tf32(a_s[row * SA_STRIDE + col]);
                afrag[mt][1] = f2tf32(a_s[(row + 8) * SA_STRIDE + col]);
                afrag[mt][2] = f2tf32(a_s[row * SA_STRIDE + col + 4]);
                afrag[mt][3] = f2tf32(a_s[(row + 8) * SA_STRIDE + col + 4]);
            }
#pragma unroll
            for (int nt = 0; nt < 4; ++nt) {
                int nn = wn + nt * 8 + (lane >> 2);
                int kk = ks * 8 + (lane & 3);
                bfrag[nt][0] = f2tf32(b_s[kk * SB_STRIDE + nn]);
                bfrag[nt][1] = f2tf32(b_s[(kk + 4) * SB_STRIDE + nn]);
            }
#pragma unroll
            for (int mt = 0; mt < 4; ++mt)
#pragma unroll
                for (int nt = 0; nt < 4; ++nt)
                    mma_m16n8k8_tf32(acc[mt][nt], afrag[mt], bfrag[nt]);
        }
        __syncthreads();
    }

    // epilogue: bias (+ optional relu), fp32 or fp16 output
#pragma unroll
    for (int mt = 0; mt < 4; ++mt) {
        int r0 = m0 + wm + mt * 16 + (lane >> 2);
#pragma unroll
        for (int nt = 0; nt < 4; ++nt) {
            int c0 = n0 + wn + nt * 8 + (lane & 3) * 2;
            float bv0 = bias[c0], bv1 = bias[c0 + 1];
            if (r0 < M) {
                float v0 = acc[mt][nt][0] + bv0;
                float v1 = acc[mt][nt][1] + bv1;
                if (RELU) { v0 = fmaxf(v0, 0.f); v1 = fmaxf(v1, 0.f); }
                if (OUT_FP16) {
                    __half2 pk = __floats2half2_rn(v0, v1);
                    *(__half2*)((__half*)Cv + (size_t)r0 * N + c0) = pk;
                } else {
                    float* C = (float*)Cv;
                    C[(size_t)r0 * N + c0] = v0;
                    C[(size_t)r0 * N + c0 + 1] = v1;
                }
            }
            if (r0 + 8 < M) {
                float v2 = acc[mt][nt][2] + bv0;
                float v3 = acc[mt][nt][3] + bv1;
                if (RELU) { v2 = fmaxf(v2, 0.f); v3 = fmaxf(v3, 0.f); }
                if (OUT_FP16) {
                    __half2 pk = __floats2half2_rn(v2, v3);
                    *(__half2*)((__half*)Cv + (size_t)(r0 + 8) * N + c0) = pk;
                } else {
                    float* C = (float*)Cv;
                    C[(size_t)(r0 + 8) * N + c0] = v2;
                    C[(size_t)(r0 + 8) * N + c0 + 1] = v3;
                }
            }
        }
    }
}

// ---------------- elementwise / small kernels ----------------
__global__ void zero_kernel(float* p, int n) {
    int i = blockIdx.x * blockDim.x + threadIdx.x;
    if (i < n) p[i] = 0.f;
}

__global__ void count_deg_kernel(const int* __restrict__ dst, float* __restrict__ cnt, int E) {
    int e = blockIdx.x * blockDim.x + threadIdx.x;
    if (e < E) atomicAdd(&cnt[dst[e]], 1.0f);
}

// h0 = x @ fc1_w + fc1_b
__global__ void node_init_kernel(const float* __restrict__ x, const float* __restrict__ w,
                                 const float* __restrict__ b, float* __restrict__ h, int Nn) {
    int i = blockIdx.x * blockDim.x + threadIdx.x;
    if (i >= Nn * 32) return;
    int n = i >> 5, o = i & 31;
    float acc = b[o];
#pragma unroll
    for (int k = 0; k < 6; ++k) acc += x[n * 6 + k] * w[k * 32 + o];
    h[i] = acc;
}

// h1 = relu(edge_attr @ k1_w + k1_b), vectorized: one thread -> 4 outputs (float4)
__global__ void __launch_bounds__(256)
edge_l1_kernel(const float* __restrict__ ea, const float* __restrict__ w,
               const float* __restrict__ b, float4* __restrict__ h1, int E) {
    int t = blockIdx.x * blockDim.x + threadIdx.x;   // over E*32
    if (t >= E * 32) return;
    int e = t >> 5, q = t & 31;                      // q: which float4 group of 128
    float a0 = ea[e * 6 + 0], a1 = ea[e * 6 + 1], a2 = ea[e * 6 + 2];
    float a3 = ea[e * 6 + 3], a4 = ea[e * 6 + 4], a5 = ea[e * 6 + 5];
    const float4* w4 = (const float4*)w;             // [6][32] float4
    const float4* b4 = (const float4*)b;
    float4 acc = b4[q];
    float4 r0 = w4[0 * 32 + q], r1 = w4[1 * 32 + q], r2 = w4[2 * 32 + q];
    float4 r3 = w4[3 * 32 + q], r4 = w4[4 * 32 + q], r5 = w4[5 * 32 + q];
    acc.x += a0 * r0.x + a1 * r1.x + a2 * r2.x + a3 * r3.x + a4 * r4.x + a5 * r5.x;
    acc.y += a0 * r0.y + a1 * r1.y + a2 * r2.y + a3 * r3.y + a4 * r4.y + a5 * r5.y;
    acc.z += a0 * r0.z + a1 * r1.z + a2 * r2.z + a3 * r3.z + a4 * r4.z + a5 * r5.z;
    acc.w += a0 * r0.w + a1 * r1.w + a2 * r2.w + a3 * r3.w + a4 * r4.w + a5 * r5.w;
    acc.x = fmaxf(acc.x, 0.f); acc.y = fmaxf(acc.y, 0.f);
    acc.z = fmaxf(acc.z, 0.f); acc.w = fmaxf(acc.w, 0.f);
    h1[(size_t)e * 32 + q] = acc;
}

// one warp per edge: msg = h[src] @ W_e (32x32 fp16), atomic scatter into aggr[dst]
// Vectorized: lane handles an o-pair; halves of the warp split even/odd rows.
__global__ void __launch_bounds__(256)
scatter_kernel(const float* __restrict__ h, const __half* __restrict__ we,
               const int* __restrict__ src, const int* __restrict__ dst,
               float* __restrict__ aggr, int E) {
    int e = blockIdx.x * 8 + (threadIdx.x >> 5);
    if (e >= E) return;
    int lane = threadIdx.x & 31;
    int s = src[e];
    int d = dst[e];
    float hv = h[s * 32 + lane];
    const __half2* W2 = (const __half2*)(we + (size_t)e * 1024);
    int r = lane >> 4;       // row parity handled by this half-warp
    int oc = lane & 15;      // output column pair
    float msg0 = 0.f, msg1 = 0.f;
#pragma unroll
    for (int i = 0; i < 32; i += 2) {
        __half2 wv = W2[(i + r) * 16 + oc];
        float2 wf = __half22float2(wv);
        float hi = __shfl_sync(0xffffffffu, hv, i + r);
        msg0 += hi * wf.x;
        msg1 += hi * wf.y;
    }
    msg0 += __shfl_xor_sync(0xffffffffu, msg0, 16);
    msg1 += __shfl_xor_sync(0xffffffffu, msg1, 16);
    if (lane < 16) {
        atomicAdd(&aggr[d * 32 + 2 * oc], msg0);
        atomicAdd(&aggr[d * 32 + 2 * oc + 1], msg1);
    }
}

// h = aggr/denom + h @ root_w + conv_b  (+ relu except last depth)
__global__ void __launch_bounds__(256)
update_kernel(const float* __restrict__ aggr, const float* __restrict__ cnt,
              const float* __restrict__ rootw, const float* __restrict__ bias,
              float* __restrict__ h, int Nn, int do_relu) {
    int n = blockIdx.x * 8 + (threadIdx.x >> 5);
    if (n >= Nn) return;
    int lane = threadIdx.x & 31;
    float hv = h[n * 32 + lane];
    float r = 0.f;
#pragma unroll
    for (int i = 0; i < 32; ++i) {
        float hi = __shfl_sync(0xffffffffu, hv, i);
        r += hi * rootw[i * 32 + lane];
    }
    float den = fmaxf(cnt[n], 1.0f);
    float v = aggr[n * 32 + lane] / den + r + bias[lane];
    if (do_relu) v = fmaxf(v, 0.f);
    h[n * 32 + lane] = v;
}

// out[n] = relu(h @ fc2 + b2) @ fc3 + b3
__global__ void __launch_bounds__(256)
readout_kernel(const float* __restrict__ h, const float* __restrict__ w2,
               const float* __restrict__ b2, const float* __restrict__ w3,
               const float* __restrict__ b3, float* __restrict__ out, int Nn) {
    int n = blockIdx.x * 8 + (threadIdx.x >> 5);
    if (n >= Nn) return;
    int lane = threadIdx.x & 31;
    float hv = h[n * 32 + lane];
    float acc = 0.f;
#pragma unroll
    for (int jt = 0; jt < 4; ++jt) {
        int j = jt * 32 + lane;
        float y = b2[j];
#pragma unroll
        for (int i = 0; i < 32; ++i) {
            float hi = __shfl_sync(0xffffffffu, hv, i);
            y += hi * w2[i * 128 + j];
        }
        y = fmaxf(y, 0.f);
        acc += y * w3[j];
    }
#pragma unroll
    for (int off = 16; off; off >>= 1) acc += __shfl_down_sync(0xffffffffu, acc, off);
    if (lane == 0) out[n] = acc + b3[0];
}

// ---------------- launch ----------------
extern "C" void kernel_launch(void* const* d_in, const int* in_sizes, int n_in,
                              void* d_out, int out_size) {
    const float* x     = (const float*)d_in[0];
    const int*   ei    = (const int*)d_in[1];
    const float* ea    = (const float*)d_in[2];
    const float* fc1w  = (const float*)d_in[3];
    const float* fc1b  = (const float*)d_in[4];
    const float* k1w   = (const float*)d_in[5];
    const float* k1b   = (const float*)d_in[6];
    const float* k2w   = (const float*)d_in[7];
    const float* k2b   = (const float*)d_in[8];
    const float* k3w   = (const float*)d_in[9];
    const float* k3b   = (const float*)d_in[10];
    const float* rootw = (const float*)d_in[11];
    const float* convb = (const float*)d_in[12];
    const float* fc2w  = (const float*)d_in[13];
    const float* fc2b  = (const float*)d_in[14];
    const float* fc3w  = (const float*)d_in[15];
    const float* fc3b  = (const float*)d_in[16];
    float* out = (float*)d_out;

    const int Nn = in_sizes[0] / 6;        // 10000
    const int E  = in_sizes[2] / 6;        // 120000
    const int* src = ei;
    const int* dst = ei + E;

    float *p_h1, *p_h2, *p_h, *p_aggr, *p_cnt;
    __half* p_we;
    cudaGetSymbolAddress((void**)&p_h1, g_h1);
    cudaGetSymbolAddress((void**)&p_h2, g_h2);
    cudaGetSymbolAddress((void**)&p_we, g_we);
    cudaGetSymbolAddress((void**)&p_h, g_h);
    cudaGetSymbolAddress((void**)&p_aggr, g_aggr);
    cudaGetSymbolAddress((void**)&p_cnt, g_cnt);

    cudaFuncSetAttribute(gemm_tf32_kernel<true, false>,
                         cudaFuncAttributeMaxDynamicSharedMemorySize, GEMM_SMEM);
    cudaFuncSetAttribute(gemm_tf32_kernel<false, true>,
                         cudaFuncAttributeMaxDynamicSharedMemorySize, GEMM_SMEM);

    // degree (scatter-mean denominator)
    zero_kernel<<<(Nn + 255) / 256, 256>>>(p_cnt, Nn);
    count_deg_kernel<<<(E + 255) / 256, 256>>>(dst, p_cnt, E);

    // node embedding
    node_init_kernel<<<(Nn * 32 + 255) / 256, 256>>>(x, fc1w, fc1b, p_h, Nn);

    // edge MLP
    edge_l1_kernel<<<(E * 32 + 255) / 256, 256>>>(ea, k1w, k1b, (float4*)p_h1, E);
    {
        dim3 grid2(2, (E + GB_BM - 1) / GB_BM);
        gemm_tf32_kernel<true, false><<<grid2, 256, GEMM_SMEM>>>(p_h1, k2w, k2b, p_h2, E, 256, 128);
        dim3 grid3(8, (E + GB_BM - 1) / GB_BM);
        gemm_tf32_kernel<false, true><<<grid3, 256, GEMM_SMEM>>>(p_h2, k3w, k3b, p_we, E, 1024, 256);
    }

    // 4 rounds of NNConv message passing
    for (int d = 0; d < 4; ++d) {
        zero_kernel<<<(Nn * 32 + 255) / 256, 256>>>(p_aggr, Nn * 32);
        scatter_kernel<<<(E + 7) / 8, 256>>>(p_h, p_we, src, dst, p_aggr, E);
        update_kernel<<<(Nn + 7) / 8, 256>>>(p_aggr, p_cnt, rootw, convb, p_h, Nn,
                                             (d < 3) ? 1 : 0);
    }

    // readout
    readout_kernel<<<(Nn + 7) / 8, 256>>>(p_h, fc2w, fc2b, fc3w, fc3b, out, Nn);
}

// round 6
// speedup vs baseline: 1.6855x; 1.3120x over previous
#include <cuda_runtime.h>
#include <cuda_fp16.h>
#include <cstdint>

// Problem constants (fixed by the dataset)
#define NN_MAX 10000
#define EE_MAX 120000

// ---------------- scratch (device globals; no allocation allowed) ----------------
__device__ __half g_h1[(size_t)EE_MAX * 128];         // 30.7 MB (fp16)
__device__ __half g_h2[(size_t)EE_MAX * 256];         // 61.4 MB (fp16)
__device__ __half g_we[(size_t)EE_MAX * 1024];        // 245.8 MB (fp16)
__device__ float g_h[(size_t)NN_MAX * 32];
__device__ float g_aggr[(size_t)NN_MAX * 32];
__device__ float g_cnt[(size_t)NN_MAX];

// ---------------- mma / ldmatrix helpers ----------------
__device__ __forceinline__ void mma_m16n8k16_f16(float* c, const uint32_t* a, const uint32_t* b) {
    asm volatile(
        "mma.sync.aligned.m16n8k16.row.col.f32.f16.f16.f32 "
        "{%0,%1,%2,%3}, {%4,%5,%6,%7}, {%8,%9}, {%0,%1,%2,%3};\n"
        : "+f"(c[0]), "+f"(c[1]), "+f"(c[2]), "+f"(c[3])
        : "r"(a[0]), "r"(a[1]), "r"(a[2]), "r"(a[3]), "r"(b[0]), "r"(b[1]));
}

__device__ __forceinline__ void ldmatrix_x4(uint32_t* r, const __half* smem_ptr) {
    uint32_t addr = (uint32_t)__cvta_generic_to_shared(smem_ptr);
    asm volatile("ldmatrix.sync.aligned.m8n8.x4.shared.b16 {%0,%1,%2,%3}, [%4];"
                 : "=r"(r[0]), "=r"(r[1]), "=r"(r[2]), "=r"(r[3]) : "r"(addr));
}

__device__ __forceinline__ void ldmatrix_x2_trans(uint32_t* r, const __half* smem_ptr) {
    uint32_t addr = (uint32_t)__cvta_generic_to_shared(smem_ptr);
    asm volatile("ldmatrix.sync.aligned.m8n8.x2.trans.shared.b16 {%0,%1}, [%2];"
                 : "=r"(r[0]), "=r"(r[1]) : "r"(addr));
}

__device__ __forceinline__ void cp_async16h(__half* smem_dst, const __half* gmem_src, int src_bytes) {
    uint32_t s = (uint32_t)__cvta_generic_to_shared(smem_dst);
    asm volatile("cp.async.cg.shared.global [%0], [%1], 16, %2;\n"
                 :: "r"(s), "l"(gmem_src), "r"(src_bytes));
}
__device__ __forceinline__ void cp_commit() { asm volatile("cp.async.commit_group;\n"); }
__device__ __forceinline__ void cp_wait1() { asm volatile("cp.async.wait_group 1;\n"); }
__device__ __forceinline__ void cp_wait0() { asm volatile("cp.async.wait_group 0;\n"); }

// ---------------- fp16 tiled GEMM: C[M,N] = op(Ah[M,K] @ Bf[K,N] + bias) ----------------
// A: fp16 global. B: fp32 global (converted to fp16 into smem). C: fp16 out.
// BM=128, BN=128, BK=32, 256 threads, warps 2(m) x 4(n), warp tile 64x32.
#define FB_BM 128
#define FB_BN 128
#define FB_BK 32
#define SAS 40    // halves per A row (32 + 8 pad); row stride 80B, 16B-aligned
#define SBS 136   // halves per B row (128 + 8 pad); row stride 272B, 16B-aligned
#define GEMM_SMEM ((2 * FB_BM * SAS + 2 * FB_BK * SBS) * 2)

__device__ __forceinline__ void f16_loadA(const __half* A, __half* sA, int m0, int kt,
                                          int tid, int M, int K) {
#pragma unroll
    for (int i = 0; i < 2; ++i) {
        int idx = i * 256 + tid;           // 0..511
        int r = idx >> 2;                  // 0..127
        int seg = idx & 3;                 // 16B segment (8 halves)
        int gr = m0 + r;
        int grc = gr < M ? gr : (M - 1);
        const __half* gp = A + (size_t)grc * K + kt * FB_BK + seg * 8;
        __half* sp = sA + r * SAS + seg * 8;
        cp_async16h(sp, gp, gr < M ? 16 : 0);
    }
}

__device__ __forceinline__ void f16_loadB_regs(const float* B, float4* breg, int n0, int kt,
                                               int tid, int N) {
#pragma unroll
    for (int i = 0; i < 4; ++i) {
        int idx = i * 256 + tid;
        int r = idx >> 5;                  // k row 0..31
        int q = idx & 31;                  // float4 col group
        breg[i] = *(const float4*)(B + (size_t)(kt * FB_BK + r) * N + n0 + q * 4);
    }
}

__device__ __forceinline__ void f16_storeB(const float4* breg, __half* sB, int tid) {
#pragma unroll
    for (int i = 0; i < 4; ++i) {
        int idx = i * 256 + tid;
        int r = idx >> 5;
        int q = idx & 31;
        __half2 lo = __floats2half2_rn(breg[i].x, breg[i].y);
        __half2 hi = __floats2half2_rn(breg[i].z, breg[i].w);
        __half2* sp = (__half2*)(sB + r * SBS + q * 4);
        sp[0] = lo;
        sp[1] = hi;
    }
}

template <bool RELU>
__global__ void __launch_bounds__(256, 2)
gemm_f16_kernel(const __half* __restrict__ A, const float* __restrict__ B,
                const float* __restrict__ bias, __half* __restrict__ C,
                int M, int N, int K) {
    extern __shared__ __half smem[];
    __half* sA = smem;                         // [2][128][SAS]
    __half* sB = smem + 2 * FB_BM * SAS;       // [2][32][SBS]

    const int tid = threadIdx.x;
    const int warp = tid >> 5;
    const int lane = tid & 31;
    const int wm = (warp >> 2) * 64;
    const int wn = (warp & 3) * 32;
    const int m0 = blockIdx.y * FB_BM;
    const int n0 = blockIdx.x * FB_BN;

    float acc[4][4][4];
#pragma unroll
    for (int mt = 0; mt < 4; ++mt)
#pragma unroll
        for (int nt = 0; nt < 4; ++nt)
#pragma unroll
            for (int r = 0; r < 4; ++r) acc[mt][nt][r] = 0.f;

    const int KT = K / FB_BK;

    float4 breg[4];
    f16_loadB_regs(B, breg, n0, 0, tid, N);
    f16_loadA(A, sA, m0, 0, tid, M, K);
    cp_commit();
    f16_storeB(breg, sB, tid);

    for (int kt = 0; kt < KT; ++kt) {
        int buf = kt & 1;
        bool has_next = (kt + 1 < KT);
        if (has_next) {
            f16_loadB_regs(B, breg, n0, kt + 1, tid, N);
            f16_loadA(A, sA + (buf ^ 1) * FB_BM * SAS, m0, kt + 1, tid, M, K);
            cp_commit();
            cp_wait1();
        } else {
            cp_wait0();
        }
        __syncthreads();
        if (has_next) f16_storeB(breg, sB + (buf ^ 1) * FB_BK * SBS, tid);

        const __half* a_s = sA + buf * FB_BM * SAS;
        const __half* b_s = sB + buf * FB_BK * SBS;

#pragma unroll
        for (int ks = 0; ks < FB_BK / 16; ++ks) {
            uint32_t afrag[4][4], bfrag[4][2];
#pragma unroll
            for (int mt = 0; mt < 4; ++mt) {
                int row = wm + mt * 16 + (lane & 15);
                int col = ks * 16 + (lane >> 4) * 8;
                ldmatrix_x4(afrag[mt], a_s + row * SAS + col);
            }
#pragma unroll
            for (int nt = 0; nt < 4; ++nt) {
                int krow = ks * 16 + (lane & 15);
                int nn = wn + nt * 8;
                ldmatrix_x2_trans(bfrag[nt], b_s + krow * SBS + nn);
            }
#pragma unroll
            for (int mt = 0; mt < 4; ++mt)
#pragma unroll
                for (int nt = 0; nt < 4; ++nt)
                    mma_m16n8k16_f16(acc[mt][nt], afrag[mt], bfrag[nt]);
        }
        __syncthreads();
    }

    // epilogue: bias (+ optional relu), fp16 output
#pragma unroll
    for (int mt = 0; mt < 4; ++mt) {
        int r0 = m0 + wm + mt * 16 + (lane >> 2);
#pragma unroll
        for (int nt = 0; nt < 4; ++nt) {
            int c0 = n0 + wn + nt * 8 + (lane & 3) * 2;
            float bv0 = bias[c0], bv1 = bias[c0 + 1];
            if (r0 < M) {
                float v0 = acc[mt][nt][0] + bv0;
                float v1 = acc[mt][nt][1] + bv1;
                if (RELU) { v0 = fmaxf(v0, 0.f); v1 = fmaxf(v1, 0.f); }
                *(__half2*)(C + (size_t)r0 * N + c0) = __floats2half2_rn(v0, v1);
            }
            if (r0 + 8 < M) {
                float v2 = acc[mt][nt][2] + bv0;
                float v3 = acc[mt][nt][3] + bv1;
                if (RELU) { v2 = fmaxf(v2, 0.f); v3 = fmaxf(v3, 0.f); }
                *(__half2*)(C + (size_t)(r0 + 8) * N + c0) = __floats2half2_rn(v2, v3);
            }
        }
    }
}

// ---------------- elementwise / small kernels ----------------
__global__ void zero_kernel(float* p, int n) {
    int i = blockIdx.x * blockDim.x + threadIdx.x;
    if (i < n) p[i] = 0.f;
}

__global__ void count_deg_kernel(const int* __restrict__ dst, float* __restrict__ cnt, int E) {
    int e = blockIdx.x * blockDim.x + threadIdx.x;
    if (e < E) atomicAdd(&cnt[dst[e]], 1.0f);
}

// h0 = x @ fc1_w + fc1_b
__global__ void node_init_kernel(const float* __restrict__ x, const float* __restrict__ w,
                                 const float* __restrict__ b, float* __restrict__ h, int Nn) {
    int i = blockIdx.x * blockDim.x + threadIdx.x;
    if (i >= Nn * 32) return;
    int n = i >> 5, o = i & 31;
    float acc = b[o];
#pragma unroll
    for (int k = 0; k < 6; ++k) acc += x[n * 6 + k] * w[k * 32 + o];
    h[i] = acc;
}

// h1 = relu(edge_attr @ k1_w + k1_b), fp16 out; one thread -> 4 outputs
__global__ void __launch_bounds__(256)
edge_l1_kernel(const float* __restrict__ ea, const float* __restrict__ w,
               const float* __restrict__ b, __half* __restrict__ h1, int E) {
    int t = blockIdx.x * blockDim.x + threadIdx.x;   // over E*32
    if (t >= E * 32) return;
    int e = t >> 5, q = t & 31;                      // q: which group of 4 of 128
    float a0 = ea[e * 6 + 0], a1 = ea[e * 6 + 1], a2 = ea[e * 6 + 2];
    float a3 = ea[e * 6 + 3], a4 = ea[e * 6 + 4], a5 = ea[e * 6 + 5];
    const float4* w4 = (const float4*)w;             // [6][32] float4
    const float4* b4 = (const float4*)b;
    float4 acc = b4[q];
    float4 r0 = w4[0 * 32 + q], r1 = w4[1 * 32 + q], r2 = w4[2 * 32 + q];
    float4 r3 = w4[3 * 32 + q], r4 = w4[4 * 32 + q], r5 = w4[5 * 32 + q];
    acc.x += a0 * r0.x + a1 * r1.x + a2 * r2.x + a3 * r3.x + a4 * r4.x + a5 * r5.x;
    acc.y += a0 * r0.y + a1 * r1.y + a2 * r2.y + a3 * r3.y + a4 * r4.y + a5 * r5.y;
    acc.z += a0 * r0.z + a1 * r1.z + a2 * r2.z + a3 * r3.z + a4 * r4.z + a5 * r5.z;
    acc.w += a0 * r0.w + a1 * r1.w + a2 * r2.w + a3 * r3.w + a4 * r4.w + a5 * r5.w;
    __half2 lo = __floats2half2_rn(fmaxf(acc.x, 0.f), fmaxf(acc.y, 0.f));
    __half2 hi = __floats2half2_rn(fmaxf(acc.z, 0.f), fmaxf(acc.w, 0.f));
    __half2* out = (__half2*)(h1 + (size_t)e * 128 + q * 4);
    out[0] = lo;
    out[1] = hi;
}

// one warp per edge: msg = h[src] @ W_e (32x32 fp16), atomic scatter into aggr[dst]
__global__ void __launch_bounds__(256)
scatter_kernel(const float* __restrict__ h, const __half* __restrict__ we,
               const int* __restrict__ src, const int* __restrict__ dst,
               float* __restrict__ aggr, int E) {
    int e = blockIdx.x * 8 + (threadIdx.x >> 5);
    if (e >= E) return;
    int lane = threadIdx.x & 31;
    int s = src[e];
    int d = dst[e];
    float hv = h[s * 32 + lane];
    const __half2* W2 = (const __half2*)(we + (size_t)e * 1024);
    int r = lane >> 4;       // row parity handled by this half-warp
    int oc = lane & 15;      // output column pair
    float msg0 = 0.f, msg1 = 0.f;
#pragma unroll
    for (int i = 0; i < 32; i += 2) {
        __half2 wv = W2[(i + r) * 16 + oc];
        float2 wf = __half22float2(wv);
        float hi = __shfl_sync(0xffffffffu, hv, i + r);
        msg0 += hi * wf.x;
        msg1 += hi * wf.y;
    }
    msg0 += __shfl_xor_sync(0xffffffffu, msg0, 16);
    msg1 += __shfl_xor_sync(0xffffffffu, msg1, 16);
    if (lane < 16) {
        atomicAdd(&aggr[d * 32 + 2 * oc], msg0);
        atomicAdd(&aggr[d * 32 + 2 * oc + 1], msg1);
    }
}

// h = aggr/denom + h @ root_w + conv_b (+ relu except last); zeroes aggr for next depth
__global__ void __launch_bounds__(256)
update_kernel(float* __restrict__ aggr, const float* __restrict__ cnt,
              const float* __restrict__ rootw, const float* __restrict__ bias,
              float* __restrict__ h, int Nn, int do_relu) {
    int n = blockIdx.x * 8 + (threadIdx.x >> 5);
    if (n >= Nn) return;
    int lane = threadIdx.x & 31;
    float hv = h[n * 32 + lane];
    float r = 0.f;
#pragma unroll
    for (int i = 0; i < 32; ++i) {
        float hi = __shfl_sync(0xffffffffu, hv, i);
        r += hi * rootw[i * 32 + lane];
    }
    float den = fmaxf(cnt[n], 1.0f);
    float a = aggr[n * 32 + lane];
    aggr[n * 32 + lane] = 0.f;               // ready for next depth
    float v = a / den + r + bias[lane];
    if (do_relu) v = fmaxf(v, 0.f);
    h[n * 32 + lane] = v;
}

// out[n] = relu(h @ fc2 + b2) @ fc3 + b3
__global__ void __launch_bounds__(256)
readout_kernel(const float* __restrict__ h, const float* __restrict__ w2,
               const float* __restrict__ b2, const float* __restrict__ w3,
               const float* __restrict__ b3, float* __restrict__ out, int Nn) {
    int n = blockIdx.x * 8 + (threadIdx.x >> 5);
    if (n >= Nn) return;
    int lane = threadIdx.x & 31;
    float hv = h[n * 32 + lane];
    float acc = 0.f;
#pragma unroll
    for (int jt = 0; jt < 4; ++jt) {
        int j = jt * 32 + lane;
        float y = b2[j];
#pragma unroll
        for (int i = 0; i < 32; ++i) {
            float hi = __shfl_sync(0xffffffffu, hv, i);
            y += hi * w2[i * 128 + j];
        }
        y = fmaxf(y, 0.f);
        acc += y * w3[j];
    }
#pragma unroll
    for (int off = 16; off; off >>= 1) acc += __shfl_down_sync(0xffffffffu, acc, off);
    if (lane == 0) out[n] = acc + b3[0];
}

// ---------------- launch ----------------
extern "C" void kernel_launch(void* const* d_in, const int* in_sizes, int n_in,
                              void* d_out, int out_size) {
    const float* x     = (const float*)d_in[0];
    const int*   ei    = (const int*)d_in[1];
    const float* ea    = (const float*)d_in[2];
    const float* fc1w  = (const float*)d_in[3];
    const float* fc1b  = (const float*)d_in[4];
    const float* k1w   = (const float*)d_in[5];
    const float* k1b   = (const float*)d_in[6];
    const float* k2w   = (const float*)d_in[7];
    const float* k2b   = (const float*)d_in[8];
    const float* k3w   = (const float*)d_in[9];
    const float* k3b   = (const float*)d_in[10];
    const float* rootw = (const float*)d_in[11];
    const float* convb = (const float*)d_in[12];
    const float* fc2w  = (const float*)d_in[13];
    const float* fc2b  = (const float*)d_in[14];
    const float* fc3w  = (const float*)d_in[15];
    const float* fc3b  = (const float*)d_in[16];
    float* out = (float*)d_out;

    const int Nn = in_sizes[0] / 6;        // 10000
    const int E  = in_sizes[2] / 6;        // 120000
    const int* src = ei;
    const int* dst = ei + E;

    float *p_h, *p_aggr, *p_cnt;
    __half *p_h1, *p_h2, *p_we;
    cudaGetSymbolAddress((void**)&p_h1, g_h1);
    cudaGetSymbolAddress((void**)&p_h2, g_h2);
    cudaGetSymbolAddress((void**)&p_we, g_we);
    cudaGetSymbolAddress((void**)&p_h, g_h);
    cudaGetSymbolAddress((void**)&p_aggr, g_aggr);
    cudaGetSymbolAddress((void**)&p_cnt, g_cnt);

    cudaFuncSetAttribute(gemm_f16_kernel<true>,
                         cudaFuncAttributeMaxDynamicSharedMemorySize, GEMM_SMEM);
    cudaFuncSetAttribute(gemm_f16_kernel<false>,
                         cudaFuncAttributeMaxDynamicSharedMemorySize, GEMM_SMEM);

    // degree (scatter-mean denominator) + zero aggr once (updates re-zero it)
    zero_kernel<<<(Nn + 255) / 256, 256>>>(p_cnt, Nn);
    count_deg_kernel<<<(E + 255) / 256, 256>>>(dst, p_cnt, E);
    zero_kernel<<<(Nn * 32 + 255) / 256, 256>>>(p_aggr, Nn * 32);

    // node embedding
    node_init_kernel<<<(Nn * 32 + 255) / 256, 256>>>(x, fc1w, fc1b, p_h, Nn);

    // edge MLP (fp16 activations, fp16 HMMA GEMMs)
    edge_l1_kernel<<<(E * 32 + 255) / 256, 256>>>(ea, k1w, k1b, p_h1, E);
    {
        dim3 grid2(2, (E + FB_BM - 1) / FB_BM);
        gemm_f16_kernel<true><<<grid2, 256, GEMM_SMEM>>>(p_h1, k2w, k2b, p_h2, E, 256, 128);
        dim3 grid3(8, (E + FB_BM - 1) / FB_BM);
        gemm_f16_kernel<false><<<grid3, 256, GEMM_SMEM>>>(p_h2, k3w, k3b, p_we, E, 1024, 256);
    }

    // 4 rounds of NNConv message passing
    for (int d = 0; d < 4; ++d) {
        scatter_kernel<<<(E + 7) / 8, 256>>>(p_h, p_we, src, dst, p_aggr, E);
        update_kernel<<<(Nn + 7) / 8, 256>>>(p_aggr, p_cnt, rootw, convb, p_h, Nn,
                                             (d < 3) ? 1 : 0);
    }

    // readout
    readout_kernel<<<(Nn + 7) / 8, 256>>>(p_h, fc2w, fc2b, fc3w, fc3b, out, Nn);
}